// round 11
// baseline (speedup 1.0000x reference)
#include <cuda_runtime.h>
#include <cstdint>

#define N_NODES 8192
#define IN_F 128
#define OUT_F 64

// Scratch (allocation-free rule: __device__ globals)
__device__ float g_z[N_NODES * OUT_F];   // z = X @ W^T + b
__device__ float g_wo[N_NODES];          // exp(lrelu(zi))      (shared off-diag att weight)
__device__ float g_wd[N_NODES];          // exp(lrelu(zi+zj))   (diagonal att weight)

__device__ __forceinline__ float lrelu(float x) {
    return x > 0.0f ? x : 0.01f * x;
}

// Kernel 1: z = X @ W^T + b, plus per-row zi = <a1, z_row>, zj = <a2, z_row>,
// folded into wo/wd. 4 rows per 256-thread block.
__global__ void __launch_bounds__(256) k_linear(
    const float* __restrict__ X, const float* __restrict__ W,
    const float* __restrict__ bias, const float* __restrict__ a1,
    const float* __restrict__ a2)
{
    const int tid = threadIdx.x;
    const int grp = tid >> 6;     // 0..3 : row within block
    const int c   = tid & 63;     // output feature
    const int row = blockIdx.x * 4 + grp;

    __shared__ float xs[4][IN_F];
    xs[grp][c]      = X[row * IN_F + c];
    xs[grp][c + 64] = X[row * IN_F + 64 + c];
    __syncthreads();

    float acc = bias[c];
    const float4* w = (const float4*)(W + c * IN_F);
#pragma unroll
    for (int k = 0; k < IN_F / 4; k++) {
        float4 wv = w[k];
        acc = fmaf(wv.x, xs[grp][4 * k + 0], acc);
        acc = fmaf(wv.y, xs[grp][4 * k + 1], acc);
        acc = fmaf(wv.z, xs[grp][4 * k + 2], acc);
        acc = fmaf(wv.w, xs[grp][4 * k + 3], acc);
    }
    g_z[row * OUT_F + c] = acc;

    float p1 = a1[c] * acc;
    float p2 = a2[c] * acc;
#pragma unroll
    for (int off = 16; off > 0; off >>= 1) {
        p1 += __shfl_down_sync(0xFFFFFFFFu, p1, off);
        p2 += __shfl_down_sync(0xFFFFFFFFu, p2, off);
    }
    __shared__ float s1[8], s2[8];
    int wid = tid >> 5;
    if ((tid & 31) == 0) { s1[wid] = p1; s2[wid] = p2; }
    __syncthreads();
    if (c == 0) {
        float zi = s1[2 * grp] + s1[2 * grp + 1];
        float zj = s2[2 * grp] + s2[2 * grp + 1];
        g_wo[row] = expf(lrelu(zi));
        g_wd[row] = expf(lrelu(zi + zj));
    }
}

// Kernel 2: one warp per row. Stream row of A (binary, evict-first so z stays
// in L2), ballot-detect nonzeros, gather-sum z rows (S), count degree, then:
//   att@z = (wo*(S - z_i) + wd*z_i) / (wo*(deg-1) + wd);  out = relu(z_i - att@z)
__global__ void __launch_bounds__(256) k_attn(
    const float* __restrict__ A, float* __restrict__ out)
{
    const int warp = threadIdx.x >> 5;
    const int lane = threadIdx.x & 31;
    const int row  = blockIdx.x * 8 + warp;

    const float4* arow = (const float4*)(A + (size_t)row * N_NODES);

    // Hoist epilogue operands: latency hidden under the main stream.
    const float zr0 = __ldg(&g_z[row * OUT_F + lane]);
    const float zr1 = __ldg(&g_z[row * OUT_F + 32 + lane]);
    const float wo  = __ldg(&g_wo[row]);
    const float wd  = __ldg(&g_wd[row]);

    // Two independent accumulator pairs: halves the serial FADD chain on the
    // gather path (mx/mz -> A-pair, my/mw -> B-pair), merged in the epilogue.
    float a0 = 0.0f, a1v = 0.0f;
    float b0 = 0.0f, b1v = 0.0f;
    int deg = 0;

#pragma unroll 1
    for (int it = 0; it < 16; ++it) {
        // MLP=4: issue all 4 streaming loads (2048B/warp) before any ballot.
        // __ldcs = evict-first: A has zero reuse; keep z resident in L2.
        float4 v0 = __ldcs(&arow[it * 128 + 0 * 32 + lane]);
        float4 v1 = __ldcs(&arow[it * 128 + 1 * 32 + lane]);
        float4 v2 = __ldcs(&arow[it * 128 + 2 * 32 + lane]);
        float4 v3 = __ldcs(&arow[it * 128 + 3 * 32 + lane]);
        const int base = it * 512;

#pragma unroll
        for (int k = 0; k < 4; k++) {
            float4 v = (k == 0) ? v0 : (k == 1) ? v1 : (k == 2) ? v2 : v3;
            const int cb = base + k * 128;
            unsigned mx = __ballot_sync(0xFFFFFFFFu, v.x != 0.0f);
            unsigned my = __ballot_sync(0xFFFFFFFFu, v.y != 0.0f);
            unsigned mz = __ballot_sync(0xFFFFFFFFu, v.z != 0.0f);
            unsigned mw = __ballot_sync(0xFFFFFFFFu, v.w != 0.0f);
            deg += __popc(mx) + __popc(my) + __popc(mz) + __popc(mw);
            while (mx) { int l = __ffs(mx) - 1; mx &= mx - 1;
                const float* zr = g_z + (size_t)(cb + 4 * l + 0) * OUT_F;
                a0  += __ldg(zr + lane); a1v += __ldg(zr + lane + 32); }
            while (my) { int l = __ffs(my) - 1; my &= my - 1;
                const float* zr = g_z + (size_t)(cb + 4 * l + 1) * OUT_F;
                b0  += __ldg(zr + lane); b1v += __ldg(zr + lane + 32); }
            while (mz) { int l = __ffs(mz) - 1; mz &= mz - 1;
                const float* zr = g_z + (size_t)(cb + 4 * l + 2) * OUT_F;
                a0  += __ldg(zr + lane); a1v += __ldg(zr + lane + 32); }
            while (mw) { int l = __ffs(mw) - 1; mw &= mw - 1;
                const float* zr = g_z + (size_t)(cb + 4 * l + 3) * OUT_F;
                b0  += __ldg(zr + lane); b1v += __ldg(zr + lane + 32); }
        }
    }

    float acc0 = a0 + b0;
    float acc1 = a1v + b1v;

    // Epilogue (self-loop guaranteed: A[i,i]=1, so deg>=1 and S includes z_i)
    float inv = 1.0f / (wo * (float)(deg - 1) + wd);
    float az0 = (wo * (acc0 - zr0) + wd * zr0) * inv;
    float az1 = (wo * (acc1 - zr1) + wd * zr1) * inv;
    out[row * OUT_F + lane]      = fmaxf(zr0 - az0, 0.0f);
    out[row * OUT_F + 32 + lane] = fmaxf(zr1 - az1, 0.0f);
}

extern "C" void kernel_launch(void* const* d_in, const int* in_sizes, int n_in,
                              void* d_out, int out_size)
{
    // Defensive input mapping by element count (deterministic, host-only):
    //   A : N*N          X : N*IN_F        W : OUT_F*IN_F
    //   b, a1, a2 : OUT_F each, kept in relative (metadata) order.
    const float* X = nullptr; const float* A = nullptr; const float* W = nullptr;
    const float* sv[3] = {nullptr, nullptr, nullptr};
    int nsv = 0;
    for (int i = 0; i < n_in; i++) {
        long long sz = in_sizes[i];
        if (sz == (long long)N_NODES * N_NODES)      A = (const float*)d_in[i];
        else if (sz == (long long)N_NODES * IN_F)    X = (const float*)d_in[i];
        else if (sz == (long long)OUT_F * IN_F)      W = (const float*)d_in[i];
        else if (sz == OUT_F && nsv < 3)             sv[nsv++] = (const float*)d_in[i];
    }
    const float* b  = sv[0];
    const float* a1 = sv[1];
    const float* a2 = sv[2];
    float* out = (float*)d_out;               // [8192, 64]

    k_linear<<<N_NODES / 4, 256>>>(X, W, b, a1, a2);
    k_attn<<<N_NODES / 8, 256>>>(A, out);
}

// round 13
// speedup vs baseline: 1.7464x; 1.7464x over previous
#include <cuda_runtime.h>
#include <cstdint>

#define N_NODES 8192
#define IN_F 128
#define OUT_F 64
#define ROWS_PB 32   // rows per k_linear block

// Scratch (allocation-free rule: __device__ globals)
__device__ float g_z[N_NODES * OUT_F];   // z = X @ W^T + b
__device__ float g_wo[N_NODES];          // exp(lrelu(zi))
__device__ float g_wd[N_NODES];          // exp(lrelu(zi+zj))

__device__ __forceinline__ float lrelu(float x) {
    return x > 0.0f ? x : 0.01f * x;
}

// Kernel 1: z = X @ W^T + b + attention scalars. W staged in smem (pad 132:
// bank (4c+4k)%32 -> 4-phase LDS.128 floor instead of 32 L1 wavefronts/LDG).
__global__ void __launch_bounds__(256) k_linear(
    const float* __restrict__ X, const float* __restrict__ W,
    const float* __restrict__ bias, const float* __restrict__ a1,
    const float* __restrict__ a2)
{
    __shared__ float ws[OUT_F * 132];
    __shared__ float xs[4][IN_F];
    __shared__ float s1[8], s2[8];

    const int tid  = threadIdx.x;
    const int grp  = tid >> 6;      // 0..3 row within group
    const int c    = tid & 63;      // output feature
    const int wid  = tid >> 5;
    const int lane = tid & 31;

    // Stage W (coalesced global reads, padded smem rows)
    for (int i = tid; i < OUT_F * IN_F; i += 256) {
        int cc = i >> 7, kk = i & 127;
        ws[cc * 132 + kk] = W[i];
    }
    const float bc  = bias[c];
    const float a1c = a1[c];
    const float a2c = a2[c];
    __syncthreads();

    const float4* wv4 = (const float4*)(ws + c * 132);

#pragma unroll 1
    for (int rg = 0; rg < ROWS_PB / 4; rg++) {
        const int row = blockIdx.x * ROWS_PB + rg * 4 + grp;
        xs[grp][c]      = X[row * IN_F + c];
        xs[grp][c + 64] = X[row * IN_F + 64 + c];
        __syncthreads();

        float acc = bc;
#pragma unroll
        for (int k = 0; k < IN_F / 4; k++) {
            float4 wv = wv4[k];
            acc = fmaf(wv.x, xs[grp][4 * k + 0], acc);
            acc = fmaf(wv.y, xs[grp][4 * k + 1], acc);
            acc = fmaf(wv.z, xs[grp][4 * k + 2], acc);
            acc = fmaf(wv.w, xs[grp][4 * k + 3], acc);
        }
        g_z[row * OUT_F + c] = acc;

        float p1 = a1c * acc;
        float p2 = a2c * acc;
#pragma unroll
        for (int off = 16; off > 0; off >>= 1) {
            p1 += __shfl_down_sync(0xFFFFFFFFu, p1, off);
            p2 += __shfl_down_sync(0xFFFFFFFFu, p2, off);
        }
        if (lane == 0) { s1[wid] = p1; s2[wid] = p2; }
        __syncthreads();
        if (c == 0) {
            float zi = s1[2 * grp] + s1[2 * grp + 1];
            float zj = s2[2 * grp] + s2[2 * grp + 1];
            g_wo[row] = expf(lrelu(zi));
            g_wd[row] = expf(lrelu(zi + zj));
        }
    }
}

// Kernel 2: one warp per row. Software-pipelined A stream (prefetch next 2KB
// before processing current -> ~8 loads in flight), ballot gather of z rows,
// deg accumulated as FADD (A entries exactly 1.0 -> exact), fused epilogue.
__global__ void __launch_bounds__(256) k_attn(
    const float* __restrict__ A, float* __restrict__ out)
{
    const int warp = threadIdx.x >> 5;
    const int lane = threadIdx.x & 31;
    const int row  = blockIdx.x * 8 + warp;

    const float4* arow = (const float4*)(A + (size_t)row * N_NODES);

    const float zr0 = __ldg(&g_z[row * OUT_F + lane]);
    const float zr1 = __ldg(&g_z[row * OUT_F + 32 + lane]);
    const float wo  = __ldg(&g_wo[row]);
    const float wd  = __ldg(&g_wd[row]);

    float a0 = 0.0f, a1v = 0.0f;    // gather accumulators (pair A)
    float b0 = 0.0f, b1v = 0.0f;    // gather accumulators (pair B)
    float dg0 = 0.0f, dg1 = 0.0f;   // degree accumulators (FMA pipe)

    // Prologue prefetch
    float4 n0 = __ldcs(&arow[0 * 32 + lane]);
    float4 n1 = __ldcs(&arow[1 * 32 + lane]);
    float4 n2 = __ldcs(&arow[2 * 32 + lane]);
    float4 n3 = __ldcs(&arow[3 * 32 + lane]);

#pragma unroll 1
    for (int it = 0; it < 16; ++it) {
        float4 v0 = n0, v1 = n1, v2 = n2, v3 = n3;
        if (it < 15) {
            const float4* p = arow + (it + 1) * 128;
            n0 = __ldcs(&p[0 * 32 + lane]);
            n1 = __ldcs(&p[1 * 32 + lane]);
            n2 = __ldcs(&p[2 * 32 + lane]);
            n3 = __ldcs(&p[3 * 32 + lane]);
        }
        const int base = it * 512;

#pragma unroll
        for (int k = 0; k < 4; k++) {
            float4 v = (k == 0) ? v0 : (k == 1) ? v1 : (k == 2) ? v2 : v3;
            const int cb = base + k * 128;
            // degree on the FMA pipe (exact: entries are 0.0 or 1.0)
            dg0 += v.x + v.y;
            dg1 += v.z + v.w;
            unsigned mx = __ballot_sync(0xFFFFFFFFu, v.x != 0.0f);
            unsigned my = __ballot_sync(0xFFFFFFFFu, v.y != 0.0f);
            unsigned mz = __ballot_sync(0xFFFFFFFFu, v.z != 0.0f);
            unsigned mw = __ballot_sync(0xFFFFFFFFu, v.w != 0.0f);
            while (mx) { int l = __ffs(mx) - 1; mx &= mx - 1;
                const float* zr = g_z + (size_t)(cb + 4 * l + 0) * OUT_F;
                a0  += __ldg(zr + lane); a1v += __ldg(zr + lane + 32); }
            while (my) { int l = __ffs(my) - 1; my &= my - 1;
                const float* zr = g_z + (size_t)(cb + 4 * l + 1) * OUT_F;
                b0  += __ldg(zr + lane); b1v += __ldg(zr + lane + 32); }
            while (mz) { int l = __ffs(mz) - 1; mz &= mz - 1;
                const float* zr = g_z + (size_t)(cb + 4 * l + 2) * OUT_F;
                a0  += __ldg(zr + lane); a1v += __ldg(zr + lane + 32); }
            while (mw) { int l = __ffs(mw) - 1; mw &= mw - 1;
                const float* zr = g_z + (size_t)(cb + 4 * l + 3) * OUT_F;
                b0  += __ldg(zr + lane); b1v += __ldg(zr + lane + 32); }
        }
    }

    float acc0 = a0 + b0;
    float acc1 = a1v + b1v;

    // Per-lane degree partials -> warp total (exact integers in fp32)
    float dgf = dg0 + dg1;
#pragma unroll
    for (int off = 16; off > 0; off >>= 1)
        dgf += __shfl_xor_sync(0xFFFFFFFFu, dgf, off);
    int deg = __float2int_rn(dgf);

    // Epilogue (self-loop guaranteed: deg>=1, S includes z_i)
    float inv = 1.0f / (wo * (float)(deg - 1) + wd);
    float az0 = (wo * (acc0 - zr0) + wd * zr0) * inv;
    float az1 = (wo * (acc1 - zr1) + wd * zr1) * inv;
    out[row * OUT_F + lane]      = fmaxf(zr0 - az0, 0.0f);
    out[row * OUT_F + 32 + lane] = fmaxf(zr1 - az1, 0.0f);
}

extern "C" void kernel_launch(void* const* d_in, const int* in_sizes, int n_in,
                              void* d_out, int out_size)
{
    // Input mapping by element count (deterministic, host-only):
    const float* X = nullptr; const float* A = nullptr; const float* W = nullptr;
    const float* sv[3] = {nullptr, nullptr, nullptr};
    int nsv = 0;
    for (int i = 0; i < n_in; i++) {
        long long sz = in_sizes[i];
        if (sz == (long long)N_NODES * N_NODES)      A = (const float*)d_in[i];
        else if (sz == (long long)N_NODES * IN_F)    X = (const float*)d_in[i];
        else if (sz == (long long)OUT_F * IN_F)      W = (const float*)d_in[i];
        else if (sz == OUT_F && nsv < 3)             sv[nsv++] = (const float*)d_in[i];
    }
    const float* b  = sv[0];
    const float* a1 = sv[1];
    const float* a2 = sv[2];
    float* out = (float*)d_out;               // [8192, 64]

    k_linear<<<N_NODES / ROWS_PB, 256>>>(X, W, b, a1, a2);
    k_attn<<<N_NODES / 8, 256>>>(A, out);
}